// round 3
// baseline (speedup 1.0000x reference)
#include <cuda_runtime.h>
#include <cstdint>

#define N_NODES 100000
#define F_IN    512
#define HID     16
#define N_CLS   40
#define E_EDGES 3200000

// -------- device scratch (no dynamic allocation allowed) --------
__device__ __align__(16) int   g_deg [N_NODES];
__device__ __align__(16) float g_dinv[N_NODES];
__device__ __align__(16) float g_h1  [N_NODES * HID];
__device__ __align__(16) float g_agg1[N_NODES * HID];
__device__ __align__(16) float g_out1[N_NODES * HID];
__device__ __align__(16) float g_agg2[N_NODES * HID];

// -------- degree / norm --------
__global__ void init_deg_kernel() {
    int i = blockIdx.x * blockDim.x + threadIdx.x;
    if (i < N_NODES) g_deg[i] = 1;  // self loop
}

__global__ void hist_kernel(const int* __restrict__ ei) {
    int e = blockIdx.x * blockDim.x + threadIdx.x;
    if (e < E_EDGES) {
        int d = ei[E_EDGES + e];   // dst row
        atomicAdd(&g_deg[d], 1);
    }
}

__global__ void dinv_kernel() {
    int i = blockIdx.x * blockDim.x + threadIdx.x;
    if (i < N_NODES) g_dinv[i] = rsqrtf((float)g_deg[i]);
}

// -------- GEMM1: h1 = x @ W1  (100000x512 @ 512x16) --------
// warp handles 8 rows; lane = (j, half): j in [0,16), half selects K range.
__global__ void gemm1_kernel(const float* __restrict__ x,
                             const float* __restrict__ W1) {
    __shared__ float Ws[HID][F_IN + 4];  // transposed, padded (conflict-free LDS.128)
    for (int i = threadIdx.x; i < F_IN * HID; i += blockDim.x) {
        int k = i >> 4;       // i / 16
        int j = i & 15;
        Ws[j][k] = W1[i];
    }
    __syncthreads();

    int warp_id = (blockIdx.x * blockDim.x + threadIdx.x) >> 5;
    int lane    = threadIdx.x & 31;
    int j       = lane & 15;
    int half    = lane >> 4;
    size_t row0 = (size_t)warp_id * 8;
    if (row0 >= N_NODES) return;

    float acc[8] = {0.f,0.f,0.f,0.f,0.f,0.f,0.f,0.f};
    const float* xb   = x + row0 * F_IN + half * 256;
    const float* wrow = &Ws[j][half * 256];

    #pragma unroll 2
    for (int kk = 0; kk < 256; kk += 4) {
        float4 w4 = *reinterpret_cast<const float4*>(wrow + kk);
        #pragma unroll
        for (int r = 0; r < 8; r++) {
            float4 xv = *reinterpret_cast<const float4*>(xb + (size_t)r * F_IN + kk);
            acc[r] = fmaf(xv.x, w4.x, acc[r]);
            acc[r] = fmaf(xv.y, w4.y, acc[r]);
            acc[r] = fmaf(xv.z, w4.z, acc[r]);
            acc[r] = fmaf(xv.w, w4.w, acc[r]);
        }
    }
    #pragma unroll
    for (int r = 0; r < 8; r++)
        acc[r] += __shfl_xor_sync(0xffffffffu, acc[r], 16);
    if (lane < 16) {
        #pragma unroll
        for (int r = 0; r < 8; r++)
            g_h1[(row0 + r) * HID + j] = acc[r];
    }
}

// -------- self-loop init: agg1 = h1 * dinv^2 --------
__global__ void selfloop1_kernel() {
    int q = blockIdx.x * blockDim.x + threadIdx.x;   // quad index over N*4
    if (q >= N_NODES * 4) return;
    int node = q >> 2;
    float dv = g_dinv[node];
    float w  = dv * dv;
    float4 v = reinterpret_cast<const float4*>(g_h1)[q];
    v.x *= w; v.y *= w; v.z *= w; v.w *= w;
    reinterpret_cast<float4*>(g_agg1)[q] = v;
}

// -------- edge scatter: out[d] += h[s] * dinv[s]*dinv[d] --------
template<int LAYER>
__global__ void scatter_kernel(const int* __restrict__ ei) {
    int e = blockIdx.x * blockDim.x + threadIdx.x;
    if (e >= E_EDGES) return;
    int s = ei[e];
    int d = ei[E_EDGES + e];
    float nrm = g_dinv[s] * g_dinv[d];
    const float* h = (LAYER == 1) ? g_h1 : g_out1;
    float*     out = (LAYER == 1) ? g_agg1 : g_agg2;
    const float4* hp = reinterpret_cast<const float4*>(h + (size_t)s * HID);
    float* op = out + (size_t)d * HID;
    #pragma unroll
    for (int q = 0; q < 4; q++) {
        float4 v = hp[q];
        atomicAdd(op + q * 4 + 0, v.x * nrm);
        atomicAdd(op + q * 4 + 1, v.y * nrm);
        atomicAdd(op + q * 4 + 2, v.z * nrm);
        atomicAdd(op + q * 4 + 3, v.w * nrm);
    }
}

// -------- relu(agg1 + b1) -> out1 ; agg2 init = out1 * dinv^2 --------
__global__ void relu_init2_kernel(const float* __restrict__ b1) {
    int q = blockIdx.x * blockDim.x + threadIdx.x;
    if (q >= N_NODES * 4) return;
    int node = q >> 2;
    int jb   = (q & 3) * 4;
    float4 v = reinterpret_cast<const float4*>(g_agg1)[q];
    v.x = fmaxf(v.x + b1[jb + 0], 0.f);
    v.y = fmaxf(v.y + b1[jb + 1], 0.f);
    v.z = fmaxf(v.z + b1[jb + 2], 0.f);
    v.w = fmaxf(v.w + b1[jb + 3], 0.f);
    reinterpret_cast<float4*>(g_out1)[q] = v;
    float dv = g_dinv[node];
    float w  = dv * dv;
    v.x *= w; v.y *= w; v.z *= w; v.w *= w;
    reinterpret_cast<float4*>(g_agg2)[q] = v;
}

// -------- z = agg2 @ W2 + b2 ; log_softmax -> out  (warp per row) --------
__global__ void gemm2_softmax_kernel(const float* __restrict__ W2,
                                     const float* __restrict__ b2,
                                     float* __restrict__ out) {
    __shared__ float W2s[HID * N_CLS];
    __shared__ float b2s[N_CLS];
    for (int i = threadIdx.x; i < HID * N_CLS; i += blockDim.x) W2s[i] = W2[i];
    if (threadIdx.x < N_CLS) b2s[threadIdx.x] = b2[threadIdx.x];
    __syncthreads();

    int row  = (blockIdx.x * blockDim.x + threadIdx.x) >> 5;
    int lane = threadIdx.x & 31;
    if (row >= N_NODES) return;

    float av = (lane < HID) ? g_agg2[(size_t)row * HID + lane] : 0.f;
    bool act = lane < 20;
    int  j0  = act ? lane : 0;

    float z0 = 0.f, z1 = 0.f;
    #pragma unroll
    for (int k = 0; k < HID; k++) {
        float ak = __shfl_sync(0xffffffffu, av, k);
        z0 = fmaf(ak, W2s[k * N_CLS + j0],      z0);
        z1 = fmaf(ak, W2s[k * N_CLS + j0 + 20], z1);
    }
    z0 += b2s[j0];
    z1 += b2s[j0 + 20];

    float m = act ? fmaxf(z0, z1) : -INFINITY;
    #pragma unroll
    for (int o = 16; o; o >>= 1) m = fmaxf(m, __shfl_xor_sync(0xffffffffu, m, o));
    float s = act ? (expf(z0 - m) + expf(z1 - m)) : 0.f;
    #pragma unroll
    for (int o = 16; o; o >>= 1) s += __shfl_xor_sync(0xffffffffu, s, o);
    float lse = m + logf(s);

    if (act) {
        out[(size_t)row * N_CLS + lane]      = z0 - lse;
        out[(size_t)row * N_CLS + lane + 20] = z1 - lse;
    }
}

// -------- launch --------
extern "C" void kernel_launch(void* const* d_in, const int* in_sizes, int n_in,
                              void* d_out, int out_size) {
    const float* x  = (const float*)d_in[0];
    const int*   ei = (const int*)d_in[1];     // int32: JAX x64 disabled
    const float* W1 = (const float*)d_in[2];
    const float* b1 = (const float*)d_in[3];
    const float* W2 = (const float*)d_in[4];
    const float* b2 = (const float*)d_in[5];
    float* out = (float*)d_out;

    const int TB = 256;
    int nblk_nodes = (N_NODES + TB - 1) / TB;
    int nblk_edges = (E_EDGES + TB - 1) / TB;
    int nblk_quads = (N_NODES * 4 + TB - 1) / TB;
    int nblk_gemm1 = (N_NODES / 8 + (TB / 32) - 1) / (TB / 32);
    int nblk_rows  = (N_NODES + (TB / 32) - 1) / (TB / 32);

    init_deg_kernel<<<nblk_nodes, TB>>>();
    hist_kernel<<<nblk_edges, TB>>>(ei);
    dinv_kernel<<<nblk_nodes, TB>>>();

    gemm1_kernel<<<nblk_gemm1, TB>>>(x, W1);

    selfloop1_kernel<<<nblk_quads, TB>>>();
    scatter_kernel<1><<<nblk_edges, TB>>>(ei);

    relu_init2_kernel<<<nblk_quads, TB>>>(b1);
    scatter_kernel<2><<<nblk_edges, TB>>>(ei);

    gemm2_softmax_kernel<<<nblk_rows, TB>>>(W2, b2, out);
}

// round 4
// speedup vs baseline: 2.1422x; 2.1422x over previous
#include <cuda_runtime.h>
#include <cstdint>

#define N_NODES 100000
#define F_IN    512
#define HID     16
#define N_CLS   40
#define E_EDGES 3200000

#define SCAN_TB   256
#define SCAN_NBLK ((N_NODES + SCAN_TB - 1) / SCAN_TB)   // 391

// -------- device scratch (no dynamic allocation allowed) --------
__device__ __align__(16) int   g_deg [N_NODES];
__device__ __align__(16) float g_dinv[N_NODES];
__device__ __align__(16) int   g_off [N_NODES + 1];
__device__ __align__(16) int   g_cur [N_NODES];
__device__ __align__(16) int   g_bsum[SCAN_NBLK];
__device__ __align__(16) int   g_bpre[SCAN_NBLK];
__device__ __align__(16) int2  g_csr [E_EDGES];          // (src, weight bits)
__device__ __align__(16) float g_h1  [N_NODES * HID];
__device__ __align__(16) float g_out1[N_NODES * HID];
__device__ __align__(16) float g_agg2[N_NODES * HID];

// -------- degree / norm --------
__global__ void init_deg_kernel() {
    int i = blockIdx.x * blockDim.x + threadIdx.x;
    if (i < N_NODES) g_deg[i] = 1;  // self loop
}

__global__ void hist_kernel(const int* __restrict__ ei) {
    int e = blockIdx.x * blockDim.x + threadIdx.x;
    if (e < E_EDGES) atomicAdd(&g_deg[ei[E_EDGES + e]], 1);
}

__global__ void dinv_kernel() {
    int i = blockIdx.x * blockDim.x + threadIdx.x;
    if (i < N_NODES) g_dinv[i] = rsqrtf((float)g_deg[i]);
}

// -------- CSR prefix scan (counts = deg - 1, i.e. edges only) --------
__global__ void scan_bsum_kernel() {
    __shared__ int sh[SCAN_TB];
    int i = blockIdx.x * SCAN_TB + threadIdx.x;
    sh[threadIdx.x] = (i < N_NODES) ? (g_deg[i] - 1) : 0;
    __syncthreads();
    for (int s = SCAN_TB / 2; s > 0; s >>= 1) {
        if (threadIdx.x < s) sh[threadIdx.x] += sh[threadIdx.x + s];
        __syncthreads();
    }
    if (threadIdx.x == 0) g_bsum[blockIdx.x] = sh[0];
}

__global__ void scan_bpre_kernel() {
    if (threadIdx.x == 0) {
        int run = 0;
        for (int b = 0; b < SCAN_NBLK; b++) { g_bpre[b] = run; run += g_bsum[b]; }
        g_off[N_NODES] = E_EDGES;
    }
}

__global__ void scan_off_kernel() {
    __shared__ int sh[2][SCAN_TB];
    int i = blockIdx.x * SCAN_TB + threadIdx.x;
    int c = (i < N_NODES) ? (g_deg[i] - 1) : 0;
    int buf = 0;
    sh[0][threadIdx.x] = c;
    __syncthreads();
    #pragma unroll
    for (int s = 1; s < SCAN_TB; s <<= 1) {
        int v = sh[buf][threadIdx.x];
        if (threadIdx.x >= s) v += sh[buf][threadIdx.x - s];
        sh[buf ^ 1][threadIdx.x] = v;
        buf ^= 1;
        __syncthreads();
    }
    if (i < N_NODES) {
        int off = g_bpre[blockIdx.x] + sh[buf][threadIdx.x] - c;  // exclusive
        g_off[i] = off;
        g_cur[i] = off;
    }
}

// -------- CSR fill: (src, norm-weight) per dst bucket --------
__global__ void fill_kernel(const int* __restrict__ ei) {
    int e = blockIdx.x * blockDim.x + threadIdx.x;
    if (e >= E_EDGES) return;
    int s = ei[e];
    int d = ei[E_EDGES + e];
    int pos = atomicAdd(&g_cur[d], 1);
    float w = g_dinv[s] * g_dinv[d];
    g_csr[pos] = make_int2(s, __float_as_int(w));
}

// -------- GEMM1: h1 = x @ W1  (100000x512 @ 512x16) --------
__global__ __launch_bounds__(512) void gemm1_kernel(const float* __restrict__ x,
                                                    const float* __restrict__ W1) {
    __shared__ float Ws[HID][F_IN + 4];  // transposed, padded
    for (int i = threadIdx.x; i < F_IN * HID; i += blockDim.x) {
        int k = i >> 4;
        int j = i & 15;
        Ws[j][k] = W1[i];
    }
    __syncthreads();

    int warp_id = (blockIdx.x * blockDim.x + threadIdx.x) >> 5;
    int lane    = threadIdx.x & 31;
    int j       = lane & 15;
    int half    = lane >> 4;
    size_t row0 = (size_t)warp_id * 8;
    if (row0 >= N_NODES) return;

    float acc[8] = {0.f,0.f,0.f,0.f,0.f,0.f,0.f,0.f};
    const float* xb   = x + row0 * F_IN + half * 256;
    const float* wrow = &Ws[j][half * 256];

    #pragma unroll 2
    for (int kk = 0; kk < 256; kk += 4) {
        float4 w4 = *reinterpret_cast<const float4*>(wrow + kk);
        #pragma unroll
        for (int r = 0; r < 8; r++) {
            float4 xv = *reinterpret_cast<const float4*>(xb + (size_t)r * F_IN + kk);
            acc[r] = fmaf(xv.x, w4.x, acc[r]);
            acc[r] = fmaf(xv.y, w4.y, acc[r]);
            acc[r] = fmaf(xv.z, w4.z, acc[r]);
            acc[r] = fmaf(xv.w, w4.w, acc[r]);
        }
    }
    #pragma unroll
    for (int r = 0; r < 8; r++)
        acc[r] += __shfl_xor_sync(0xffffffffu, acc[r], 16);
    if (lane < 16) {
        #pragma unroll
        for (int r = 0; r < 8; r++)
            g_h1[(row0 + r) * HID + j] = acc[r];
    }
}

// -------- pull aggregation: out[d] = sum_e h[src_e]*w_e + h[d]*dinv[d]^2 --------
// LAYER 1: reads g_h1, adds b1, relu -> g_out1
// LAYER 2: reads g_out1 -> g_agg2
template<int LAYER>
__global__ void gather_kernel(const float* __restrict__ b1) {
    int warp = (blockIdx.x * blockDim.x + threadIdx.x) >> 5;
    if (warp >= N_NODES) return;
    int lane = threadIdx.x & 31;
    int j = lane & 15;
    int p = lane >> 4;

    const float* __restrict__ h = (LAYER == 1) ? g_h1 : g_out1;
    int beg = g_off[warp];
    int end = g_off[warp + 1];

    float acc0 = 0.f, acc1 = 0.f;
    int e = beg + p;
    // 2x unroll per p-slot (4 edges in flight per warp-iteration)
    for (; e + 2 < end; e += 4) {
        int2 r0 = g_csr[e];
        int2 r1 = g_csr[e + 2];
        acc0 = fmaf(h[(size_t)r0.x * HID + j], __int_as_float(r0.y), acc0);
        acc1 = fmaf(h[(size_t)r1.x * HID + j], __int_as_float(r1.y), acc1);
    }
    if (e < end) {
        int2 r0 = g_csr[e];
        acc0 = fmaf(h[(size_t)r0.x * HID + j], __int_as_float(r0.y), acc0);
    }
    float acc = acc0 + acc1;
    acc += __shfl_xor_sync(0xffffffffu, acc, 16);

    if (p == 0) {
        float dv = g_dinv[warp];
        acc = fmaf(h[(size_t)warp * HID + j], dv * dv, acc);  // self loop
        if (LAYER == 1) {
            acc = fmaxf(acc + b1[j], 0.f);                    // + bias, relu
            g_out1[(size_t)warp * HID + j] = acc;
        } else {
            g_agg2[(size_t)warp * HID + j] = acc;
        }
    }
}

// -------- z = agg2 @ W2 + b2 ; log_softmax -> out  (warp per row) --------
__global__ void gemm2_softmax_kernel(const float* __restrict__ W2,
                                     const float* __restrict__ b2,
                                     float* __restrict__ out) {
    __shared__ float W2s[HID * N_CLS];
    __shared__ float b2s[N_CLS];
    for (int i = threadIdx.x; i < HID * N_CLS; i += blockDim.x) W2s[i] = W2[i];
    if (threadIdx.x < N_CLS) b2s[threadIdx.x] = b2[threadIdx.x];
    __syncthreads();

    int row  = (blockIdx.x * blockDim.x + threadIdx.x) >> 5;
    int lane = threadIdx.x & 31;
    if (row >= N_NODES) return;

    float av = (lane < HID) ? g_agg2[(size_t)row * HID + lane] : 0.f;
    bool act = lane < 20;
    int  j0  = act ? lane : 0;

    float z0 = 0.f, z1 = 0.f;
    #pragma unroll
    for (int k = 0; k < HID; k++) {
        float ak = __shfl_sync(0xffffffffu, av, k);
        z0 = fmaf(ak, W2s[k * N_CLS + j0],      z0);
        z1 = fmaf(ak, W2s[k * N_CLS + j0 + 20], z1);
    }
    z0 += b2s[j0];
    z1 += b2s[j0 + 20];

    float m = act ? fmaxf(z0, z1) : -INFINITY;
    #pragma unroll
    for (int o = 16; o; o >>= 1) m = fmaxf(m, __shfl_xor_sync(0xffffffffu, m, o));
    float s = act ? (expf(z0 - m) + expf(z1 - m)) : 0.f;
    #pragma unroll
    for (int o = 16; o; o >>= 1) s += __shfl_xor_sync(0xffffffffu, s, o);
    float lse = m + logf(s);

    if (act) {
        out[(size_t)row * N_CLS + lane]      = z0 - lse;
        out[(size_t)row * N_CLS + lane + 20] = z1 - lse;
    }
}

// -------- launch --------
extern "C" void kernel_launch(void* const* d_in, const int* in_sizes, int n_in,
                              void* d_out, int out_size) {
    const float* x  = (const float*)d_in[0];
    const int*   ei = (const int*)d_in[1];     // int32 (JAX x64 disabled)
    const float* W1 = (const float*)d_in[2];
    const float* b1 = (const float*)d_in[3];
    const float* W2 = (const float*)d_in[4];
    const float* b2 = (const float*)d_in[5];
    float* out = (float*)d_out;

    const int TB = 256;
    int nblk_nodes = (N_NODES + TB - 1) / TB;
    int nblk_edges = (E_EDGES + TB - 1) / TB;
    int nblk_gemm1 = (N_NODES / 8 + (512 / 32) - 1) / (512 / 32);
    int nblk_rows  = (N_NODES + (TB / 32) - 1) / (TB / 32);  // warp per node

    init_deg_kernel<<<nblk_nodes, TB>>>();
    hist_kernel<<<nblk_edges, TB>>>(ei);
    dinv_kernel<<<nblk_nodes, TB>>>();

    scan_bsum_kernel<<<SCAN_NBLK, SCAN_TB>>>();
    scan_bpre_kernel<<<1, 32>>>();
    scan_off_kernel<<<SCAN_NBLK, SCAN_TB>>>();
    fill_kernel<<<nblk_edges, TB>>>(ei);

    gemm1_kernel<<<nblk_gemm1, 512>>>(x, W1);

    gather_kernel<1><<<nblk_rows, TB>>>(b1);
    gather_kernel<2><<<nblk_rows, TB>>>(b1);

    gemm2_softmax_kernel<<<nblk_rows, TB>>>(W2, b2, out);
}

// round 5
// speedup vs baseline: 2.2365x; 1.0440x over previous
#include <cuda_runtime.h>
#include <cstdint>

#define N_NODES 100000
#define F_IN    512
#define HID     16
#define N_CLS   40
#define E_EDGES 3200000

#define SCAN_TB   256
#define SCAN_NBLK ((N_NODES + SCAN_TB - 1) / SCAN_TB)   // 391

// packed fp32x2 FMA (Blackwell): d = a*b + c elementwise on 2 packed floats
#define FMA2(d, a, b, c) \
    asm("fma.rn.f32x2 %0, %1, %2, %3;" : "=l"(d) : "l"(a), "l"(b), "l"(c))

// -------- device scratch (no dynamic allocation allowed) --------
__device__ __align__(16) int   g_deg [N_NODES];
__device__ __align__(16) float g_dinv[N_NODES];
__device__ __align__(16) int   g_off [N_NODES + 1];
__device__ __align__(16) int   g_cur [N_NODES];
__device__ __align__(16) int   g_bsum[SCAN_NBLK];
__device__ __align__(16) int   g_bpre[SCAN_NBLK];
__device__ __align__(16) int2  g_csr [E_EDGES];          // (src, weight bits)
__device__ __align__(16) float g_h1  [N_NODES * HID];
__device__ __align__(16) float g_out1[N_NODES * HID];

// -------- degree / norm --------
__global__ void init_deg_kernel() {
    int i = blockIdx.x * blockDim.x + threadIdx.x;
    if (i < N_NODES) g_deg[i] = 1;  // self loop
}

__global__ void hist_kernel(const int* __restrict__ ei) {
    int e = blockIdx.x * blockDim.x + threadIdx.x;
    if (e < E_EDGES) atomicAdd(&g_deg[ei[E_EDGES + e]], 1);
}

__global__ void dinv_kernel() {
    int i = blockIdx.x * blockDim.x + threadIdx.x;
    if (i < N_NODES) g_dinv[i] = rsqrtf((float)g_deg[i]);
}

// -------- CSR prefix scan (counts = deg - 1, i.e. edges only) --------
__global__ void scan_bsum_kernel() {
    __shared__ int sh[SCAN_TB];
    int i = blockIdx.x * SCAN_TB + threadIdx.x;
    sh[threadIdx.x] = (i < N_NODES) ? (g_deg[i] - 1) : 0;
    __syncthreads();
    for (int s = SCAN_TB / 2; s > 0; s >>= 1) {
        if (threadIdx.x < s) sh[threadIdx.x] += sh[threadIdx.x + s];
        __syncthreads();
    }
    if (threadIdx.x == 0) g_bsum[blockIdx.x] = sh[0];
}

// single block, 512 threads: exclusive scan over SCAN_NBLK block sums
__global__ void scan_bpre_kernel() {
    __shared__ int sh[2][512];
    int t = threadIdx.x;
    int c = (t < SCAN_NBLK) ? g_bsum[t] : 0;
    int buf = 0;
    sh[0][t] = c;
    __syncthreads();
    #pragma unroll
    for (int s = 1; s < 512; s <<= 1) {
        int v = sh[buf][t];
        if (t >= s) v += sh[buf][t - s];
        sh[buf ^ 1][t] = v;
        buf ^= 1;
        __syncthreads();
    }
    if (t < SCAN_NBLK) g_bpre[t] = sh[buf][t] - c;   // exclusive
    if (t == 0) g_off[N_NODES] = E_EDGES;
}

__global__ void scan_off_kernel() {
    __shared__ int sh[2][SCAN_TB];
    int i = blockIdx.x * SCAN_TB + threadIdx.x;
    int c = (i < N_NODES) ? (g_deg[i] - 1) : 0;
    int buf = 0;
    sh[0][threadIdx.x] = c;
    __syncthreads();
    #pragma unroll
    for (int s = 1; s < SCAN_TB; s <<= 1) {
        int v = sh[buf][threadIdx.x];
        if (threadIdx.x >= s) v += sh[buf][threadIdx.x - s];
        sh[buf ^ 1][threadIdx.x] = v;
        buf ^= 1;
        __syncthreads();
    }
    if (i < N_NODES) {
        int off = g_bpre[blockIdx.x] + sh[buf][threadIdx.x] - c;  // exclusive
        g_off[i] = off;
        g_cur[i] = off;
    }
}

// -------- CSR fill: (src, norm-weight) per dst bucket --------
__global__ void fill_kernel(const int* __restrict__ ei) {
    int e = blockIdx.x * blockDim.x + threadIdx.x;
    if (e >= E_EDGES) return;
    int s = ei[e];
    int d = ei[E_EDGES + e];
    int pos = atomicAdd(&g_cur[d], 1);
    float w = g_dinv[s] * g_dinv[d];
    g_csr[pos] = make_int2(s, __float_as_int(w));
}

// -------- GEMM1: h1 = x @ W1  (100000x512 @ 512x16), packed f32x2 --------
__global__ __launch_bounds__(256) void gemm1_kernel(const float* __restrict__ x,
                                                    const float* __restrict__ W1) {
    __shared__ float Ws[HID][F_IN + 4];  // transposed, padded
    for (int i = threadIdx.x; i < F_IN * HID; i += blockDim.x) {
        int k = i >> 4;
        int j = i & 15;
        Ws[j][k] = W1[i];
    }
    __syncthreads();

    int warp_id = (blockIdx.x * blockDim.x + threadIdx.x) >> 5;
    int lane    = threadIdx.x & 31;
    int j       = lane & 15;
    int half    = lane >> 4;
    size_t row0 = (size_t)warp_id * 8;
    if (row0 >= N_NODES) return;

    unsigned long long acc2[8] = {0ull,0ull,0ull,0ull,0ull,0ull,0ull,0ull};
    const float* xb   = x + row0 * F_IN + half * 256;
    const float* wrow = &Ws[j][half * 256];

    #pragma unroll 4
    for (int kk = 0; kk < 256; kk += 4) {
        ulonglong2 w2 = *reinterpret_cast<const ulonglong2*>(wrow + kk);
        #pragma unroll
        for (int r = 0; r < 8; r++) {
            ulonglong2 xv = *reinterpret_cast<const ulonglong2*>(xb + (size_t)r * F_IN + kk);
            FMA2(acc2[r], xv.x, w2.x, acc2[r]);
            FMA2(acc2[r], xv.y, w2.y, acc2[r]);
        }
    }
    #pragma unroll
    for (int r = 0; r < 8; r++) {
        float lo = __uint_as_float((unsigned)(acc2[r] & 0xffffffffull));
        float hi = __uint_as_float((unsigned)(acc2[r] >> 32));
        float acc = lo + hi;
        acc += __shfl_xor_sync(0xffffffffu, acc, 16);
        if (lane < 16) g_h1[(row0 + r) * HID + j] = acc;
    }
}

// -------- layer-1 pull aggregation + bias + relu -> g_out1 --------
__global__ void gather1_kernel(const float* __restrict__ b1) {
    int warp = (blockIdx.x * blockDim.x + threadIdx.x) >> 5;
    if (warp >= N_NODES) return;
    int lane = threadIdx.x & 31;
    int j = lane & 15;
    int p = lane >> 4;

    int beg = g_off[warp];
    int end = g_off[warp + 1];

    float a0 = 0.f, a1 = 0.f, a2 = 0.f, a3 = 0.f;
    int e = beg + p;
    for (; e + 6 < end; e += 8) {
        int2 r0 = g_csr[e];
        int2 r1 = g_csr[e + 2];
        int2 r2 = g_csr[e + 4];
        int2 r3 = g_csr[e + 6];
        a0 = fmaf(g_h1[(size_t)r0.x * HID + j], __int_as_float(r0.y), a0);
        a1 = fmaf(g_h1[(size_t)r1.x * HID + j], __int_as_float(r1.y), a1);
        a2 = fmaf(g_h1[(size_t)r2.x * HID + j], __int_as_float(r2.y), a2);
        a3 = fmaf(g_h1[(size_t)r3.x * HID + j], __int_as_float(r3.y), a3);
    }
    for (; e < end; e += 2) {
        int2 r0 = g_csr[e];
        a0 = fmaf(g_h1[(size_t)r0.x * HID + j], __int_as_float(r0.y), a0);
    }
    float acc = (a0 + a1) + (a2 + a3);
    acc += __shfl_xor_sync(0xffffffffu, acc, 16);

    if (p == 0) {
        float dv = g_dinv[warp];
        acc = fmaf(g_h1[(size_t)warp * HID + j], dv * dv, acc);  // self loop
        acc = fmaxf(acc + b1[j], 0.f);                           // bias + relu
        g_out1[(size_t)warp * HID + j] = acc;
    }
}

// -------- layer-2 aggregation fused with GEMM2 + bias + log_softmax --------
__global__ void gather2_softmax_kernel(const float* __restrict__ W2,
                                       const float* __restrict__ b2,
                                       float* __restrict__ out) {
    __shared__ float W2s[HID * N_CLS];
    __shared__ float b2s[N_CLS];
    for (int i = threadIdx.x; i < HID * N_CLS; i += blockDim.x) W2s[i] = W2[i];
    if (threadIdx.x < N_CLS) b2s[threadIdx.x] = b2[threadIdx.x];
    __syncthreads();

    int warp = (blockIdx.x * blockDim.x + threadIdx.x) >> 5;
    if (warp >= N_NODES) return;
    int lane = threadIdx.x & 31;
    int j = lane & 15;
    int p = lane >> 4;

    int beg = g_off[warp];
    int end = g_off[warp + 1];

    float a0 = 0.f, a1 = 0.f, a2 = 0.f, a3 = 0.f;
    int e = beg + p;
    for (; e + 6 < end; e += 8) {
        int2 r0 = g_csr[e];
        int2 r1 = g_csr[e + 2];
        int2 r2 = g_csr[e + 4];
        int2 r3 = g_csr[e + 6];
        a0 = fmaf(g_out1[(size_t)r0.x * HID + j], __int_as_float(r0.y), a0);
        a1 = fmaf(g_out1[(size_t)r1.x * HID + j], __int_as_float(r1.y), a1);
        a2 = fmaf(g_out1[(size_t)r2.x * HID + j], __int_as_float(r2.y), a2);
        a3 = fmaf(g_out1[(size_t)r3.x * HID + j], __int_as_float(r3.y), a3);
    }
    for (; e < end; e += 2) {
        int2 r0 = g_csr[e];
        a0 = fmaf(g_out1[(size_t)r0.x * HID + j], __int_as_float(r0.y), a0);
    }
    float av = (a0 + a1) + (a2 + a3);
    av += __shfl_xor_sync(0xffffffffu, av, 16);   // both halves now hold full sum
    float dv = g_dinv[warp];
    av = fmaf(g_out1[(size_t)warp * HID + j], dv * dv, av);  // self loop

    // av[j] now replicated on lanes j and j+16. mat-vec 16x40 + log_softmax.
    bool act = lane < 20;
    int  j0  = act ? lane : 0;

    float z0 = 0.f, z1 = 0.f;
    #pragma unroll
    for (int k = 0; k < HID; k++) {
        float ak = __shfl_sync(0xffffffffu, av, k);   // lane k holds av[k]
        z0 = fmaf(ak, W2s[k * N_CLS + j0],      z0);
        z1 = fmaf(ak, W2s[k * N_CLS + j0 + 20], z1);
    }
    z0 += b2s[j0];
    z1 += b2s[j0 + 20];

    float m = act ? fmaxf(z0, z1) : -INFINITY;
    #pragma unroll
    for (int o = 16; o; o >>= 1) m = fmaxf(m, __shfl_xor_sync(0xffffffffu, m, o));
    float s = act ? (expf(z0 - m) + expf(z1 - m)) : 0.f;
    #pragma unroll
    for (int o = 16; o; o >>= 1) s += __shfl_xor_sync(0xffffffffu, s, o);
    float lse = m + logf(s);

    if (act) {
        out[(size_t)warp * N_CLS + lane]      = z0 - lse;
        out[(size_t)warp * N_CLS + lane + 20] = z1 - lse;
    }
}

// -------- launch --------
extern "C" void kernel_launch(void* const* d_in, const int* in_sizes, int n_in,
                              void* d_out, int out_size) {
    const float* x  = (const float*)d_in[0];
    const int*   ei = (const int*)d_in[1];     // int32 (JAX x64 disabled)
    const float* W1 = (const float*)d_in[2];
    const float* b1 = (const float*)d_in[3];
    const float* W2 = (const float*)d_in[4];
    const float* b2 = (const float*)d_in[5];
    float* out = (float*)d_out;

    const int TB = 256;
    int nblk_nodes = (N_NODES + TB - 1) / TB;
    int nblk_edges = (E_EDGES + TB - 1) / TB;
    int nblk_gemm1 = (N_NODES / 8 + (TB / 32) - 1) / (TB / 32);
    int nblk_rows  = (N_NODES + (TB / 32) - 1) / (TB / 32);  // warp per node

    init_deg_kernel<<<nblk_nodes, TB>>>();
    hist_kernel<<<nblk_edges, TB>>>(ei);
    dinv_kernel<<<nblk_nodes, TB>>>();

    scan_bsum_kernel<<<SCAN_NBLK, SCAN_TB>>>();
    scan_bpre_kernel<<<1, 512>>>();
    scan_off_kernel<<<SCAN_NBLK, SCAN_TB>>>();
    fill_kernel<<<nblk_edges, TB>>>(ei);

    gemm1_kernel<<<nblk_gemm1, TB>>>(x, W1);

    gather1_kernel<<<nblk_rows, TB>>>(b1);
    gather2_softmax_kernel<<<nblk_rows, TB>>>(W2, b2, out);
}